// round 14
// baseline (speedup 1.0000x reference)
#include <cuda_runtime.h>
#include <cstdint>

#define BB 64
#define SS 512
#define HH 1024
#define LL 9
#define NC 32
#define CHUNK 16

#define RPW 2            // rows per warp in k_logits
#define RPB 16           // rows per block (8 warps * 2)

// scratch (static __device__ — no allocations)
__device__ float g_logits[BB*SS*LL];     // [B,S,L] fc outputs
__device__ float g_chunks[BB*NC*81];     // per-(batch,chunk) 9x9 transfer matrices
__device__ float g_pb[BB];               // per-batch (norm - score)
__device__ int   g_cnt[BB];              // per-batch chunk-completion counters
__device__ int   g_ticket;               // global ticket for final mean

// ---------------------------------------------------------------------------
// Kernel 1: logits[b,s,j] = dot(inputs[b,s,:], W[j,:]) + bias[j]
// 8 warps x 2 rows = 16 rows/block. W (36 KB) in SMEM.
// Register double-buffer: 4 LDG.128 for the NEXT 2 k-iters issued before
// computing the current 2 -> 8 loads in flight. Bit-exact logits.
// Also resets the ticket counters used by the fused CRF kernel.
// ---------------------------------------------------------------------------
__global__ __launch_bounds__(256, 4) void k_logits(const float* __restrict__ X,
                                                   const float* __restrict__ W,
                                                   const float* __restrict__ bias) {
    if (blockIdx.x == 0) {
        if (threadIdx.x < BB) g_cnt[threadIdx.x] = 0;
        if (threadIdx.x == BB) g_ticket = 0;
    }

    __shared__ float4 Wsh[LL*(HH/4)];   // 9*256 float4 = 36 KB
    const float4* W4 = reinterpret_cast<const float4*>(W);
    for (int idx = threadIdx.x; idx < LL*(HH/4); idx += 256) Wsh[idx] = W4[idx];
    __syncthreads();

    const int warp = threadIdx.x >> 5;
    const int lane = threadIdx.x & 31;
    const int row0 = blockIdx.x * RPB + warp * RPW;
    const float4* Xr0 = reinterpret_cast<const float4*>(X) + (size_t)row0 * (HH/4);
    const float4* Xr1 = Xr0 + (HH/4);

    float acc[RPW][LL];
    #pragma unroll
    for (int r = 0; r < RPW; r++)
        #pragma unroll
        for (int j = 0; j < LL; j++) acc[r][j] = 0.f;

    float4 cur[2][RPW], nxt[2][RPW];
    cur[0][0] = Xr0[lane];        cur[0][1] = Xr1[lane];
    cur[1][0] = Xr0[32 + lane];   cur[1][1] = Xr1[32 + lane];

    #pragma unroll
    for (int g = 0; g < 4; g++) {
        if (g < 3) {               // prefetch k-iters 2g+2, 2g+3
            const int c0 = (2*g + 2)*32 + lane;
            nxt[0][0] = Xr0[c0];      nxt[0][1] = Xr1[c0];
            nxt[1][0] = Xr0[c0 + 32]; nxt[1][1] = Xr1[c0 + 32];
        }
        #pragma unroll
        for (int u = 0; u < 2; u++) {
            const int col = (2*g + u)*32 + lane;
            #pragma unroll
            for (int j = 0; j < LL; j++) {
                const float4 w = Wsh[j*(HH/4) + col];
                #pragma unroll
                for (int r = 0; r < RPW; r++) {
                    acc[r][j] += cur[u][r].x*w.x;
                    acc[r][j] += cur[u][r].y*w.y;
                    acc[r][j] += cur[u][r].z*w.z;
                    acc[r][j] += cur[u][r].w*w.w;
                }
            }
        }
        #pragma unroll
        for (int u = 0; u < 2; u++)
            #pragma unroll
            for (int r = 0; r < RPW; r++) cur[u][r] = nxt[u][r];
    }

    #pragma unroll
    for (int r = 0; r < RPW; r++)
        #pragma unroll
        for (int j = 0; j < LL; j++) {
            float v = acc[r][j];
            v += __shfl_xor_sync(0xffffffffu, v, 16);
            v += __shfl_xor_sync(0xffffffffu, v, 8);
            v += __shfl_xor_sync(0xffffffffu, v, 4);
            v += __shfl_xor_sync(0xffffffffu, v, 2);
            v += __shfl_xor_sync(0xffffffffu, v, 1);
            acc[r][j] = v;
        }

    if (lane < LL) {
        const float bj = __ldg(&bias[lane]);
        #pragma unroll
        for (int r = 0; r < RPW; r++)
            g_logits[(size_t)(row0 + r)*LL + lane] = acc[r][lane] + bj;
    }
}

// monotone int key for fp32 max (order-preserving bijection)
__device__ __forceinline__ int f2key(float x) {
    int b = __float_as_int(x);
    return b ^ ((b >> 31) | 0x80000000);
}
__device__ __forceinline__ float key2f(int k) {
    return __int_as_float(k ^ ((k >= 0) ? 0xFFFFFFFF : 0x80000000));
}

// ---------------------------------------------------------------------------
// Kernel 2 (fused chunks + final + mean):
// Each block folds one (batch, chunk of 16) into a 9x9 transfer matrix.
// Probability-domain step: per lane 1 exp + 1 log (group max via redux.max
// on a monotone int key; inner sum = dot of gathered exps with exp(trans)).
// The LAST block per batch composes 32 matrices + gold score; globally-last
// batch writes the mean. Labels are int32 (JAX x64 off).
// ---------------------------------------------------------------------------
__global__ __launch_bounds__(96) void k_crf(const float* __restrict__ trans,
                                            const int* __restrict__ mask,
                                            const int* __restrict__ labels,
                                            const float* __restrict__ startv,
                                            const float* __restrict__ endv,
                                            float* __restrict__ out) {
    __shared__ float emit_sh[CHUNK][LL];
    __shared__ int   mask_sh[CHUNK];

    const int b  = blockIdx.x / NC;
    const int c  = blockIdx.x % NC;
    const int t0 = 1 + c * CHUNK;
    const int n  = min(SS, t0 + CHUNK) - t0;   // 16 (last chunk 15)
    const int tid  = threadIdx.x;
    const int warp = tid >> 5;
    const int lane = tid & 31;

    for (int idx = tid; idx < n * LL; idx += 96)
        emit_sh[idx / LL][idx % LL] =
            g_logits[((size_t)b*SS + t0 + idx/LL)*LL + (idx % LL)];
    for (int idx = tid; idx < n; idx += 96)
        mask_sh[idx] = mask[b*SS + t0 + idx];
    __syncthreads();

    const bool act   = lane < 27;
    const int  grp   = lane / LL;             // 0..3 (3 = inactive tail)
    const int  base  = grp * LL;              // first lane of this row group
    const int  i     = warp * 3 + grp;        // row (valid when act)
    const int  j     = lane % LL;             // column
    const unsigned gmask = (grp < 3) ? (0x1FFu << (grp * LL)) : 0xF8000000u;

    float tcol[LL], Ecol[LL];                 // trans[k][j], exp(trans[k][j])
    #pragma unroll
    for (int k = 0; k < LL; k++) {
        tcol[k] = trans[k*LL + j];
        Ecol[k] = __expf(tcol[k]);
    }

    // init with first step t0: M[i][j] = trans[i][j] + emit[j], or identity
    float cur = 0.f;
    if (act)
        cur = (mask_sh[0] > 0) ? (trans[i*LL + j] + emit_sh[0][j])
                               : ((i == j) ? 0.f : -1e30f);

    for (int s = 1; s < n; s++) {
        const int   kmax = __reduce_max_sync(gmask, f2key(cur));
        const float mx   = key2f(kmax);                 // row max (exact)
        const float e    = __expf(cur - mx);
        float p[LL];
        #pragma unroll
        for (int k = 0; k < LL; k++)
            p[k] = __shfl_sync(0xffffffffu, e, base + k) * Ecol[k];
        const float s01 = p[0]+p[1], s23 = p[2]+p[3];
        const float s45 = p[4]+p[5], s67 = p[6]+p[7];
        const float ssum = ((s01+s23)+(s45+s67)) + p[8];
        const float newv = emit_sh[s][j] + mx + __logf(ssum);
        cur = (mask_sh[s] > 0) ? newv : cur;            // exact copy when masked
    }

    if (act) g_chunks[(size_t)(b*NC + c)*81 + i*LL + j] = cur;

    // ---- per-batch ticket: last chunk block of batch b does the finale ----
    __threadfence();
    __syncthreads();
    __shared__ int is_last;
    if (tid == 0) is_last = (atomicAdd(&g_cnt[b], 1) == NC - 1);
    __syncthreads();
    if (!is_last) return;
    __threadfence();   // order the other blocks' g_chunks stores before reads

    __shared__ float redf[96];
    __shared__ int   redi[96];
    __shared__ float alpha_sh[LL];

    float part = 0.f; int cnt = 0;
    for (int t = tid; t < SS; t += 96) {
        const int tag = labels[(size_t)b*SS + t];
        const int mi  = mask[b*SS + t];
        const float m = (mi > 0) ? 1.f : 0.f;
        cnt += (mi > 0);
        part += m * g_logits[((size_t)b*SS + t)*LL + tag];
        if (t >= 1) {
            const int tagp = labels[(size_t)b*SS + t - 1];
            part += m * trans[tagp*LL + tag];
        }
    }
    redf[tid] = part; redi[tid] = cnt;
    __syncthreads();
    for (int s2 = 64; s2 > 0; s2 >>= 1) {
        if (tid < s2 && tid + s2 < 96) {
            redf[tid] += redf[tid + s2];
            redi[tid] += redi[tid + s2];
        }
        __syncthreads();
    }

    // alpha0 = feats[0] + start (mask not applied at t=0, per reference)
    if (tid < LL) alpha_sh[tid] = g_logits[((size_t)b*SS)*LL + tid] + startv[tid];
    __syncthreads();

    for (int cc = 0; cc < NC; cc++) {
        float newv = 0.f;
        if (tid < LL) {
            const float* P = &g_chunks[(size_t)(b*NC + cc)*81];
            float v[LL];
            float mx = -1e30f;
            #pragma unroll
            for (int k = 0; k < LL; k++) {
                v[k] = alpha_sh[k] + P[k*LL + tid];
                mx = fmaxf(mx, v[k]);
            }
            float s = 0.f;
            #pragma unroll
            for (int k = 0; k < LL; k++) s += __expf(v[k] - mx);
            newv = mx + __logf(s);
        }
        __syncthreads();
        if (tid < LL) alpha_sh[tid] = newv;
        __syncthreads();
    }

    if (tid == 0) {
        float mx = -1e30f;
        #pragma unroll
        for (int jj = 0; jj < LL; jj++) mx = fmaxf(mx, alpha_sh[jj] + endv[jj]);
        float s = 0.f;
        #pragma unroll
        for (int jj = 0; jj < LL; jj++) s += __expf(alpha_sh[jj] + endv[jj] - mx);
        const float norm = mx + __logf(s);

        int last_idx = redi[0] - 1; if (last_idx < 0) last_idx = 0;
        const int tag0 = labels[(size_t)b*SS];
        const int tagL = labels[(size_t)b*SS + last_idx];
        g_pb[b] = norm - (redf[0] + startv[tag0] + endv[tagL]);

        __threadfence();
        const int t2 = atomicAdd(&g_ticket, 1);
        if (t2 == BB - 1) {           // globally last batch: reduce to scalar
            __threadfence();
            float sum = 0.f;
            #pragma unroll
            for (int ib = 0; ib < BB; ib++) sum += g_pb[ib];
            out[0] = sum * (1.f / BB);
        }
    }
}

extern "C" void kernel_launch(void* const* d_in, const int* in_sizes, int n_in,
                              void* d_out, int out_size) {
    const float* X      = (const float*)d_in[0];
    const int*   labels = (const int*)  d_in[1];   // int32 on device (JAX x64 off)
    const int*   mask   = (const int*)  d_in[2];
    const float* W      = (const float*)d_in[3];
    const float* bias   = (const float*)d_in[4];
    const float* trans  = (const float*)d_in[5];
    const float* startv = (const float*)d_in[6];
    const float* endv   = (const float*)d_in[7];

    k_logits<<<(BB*SS)/RPB, 256>>>(X, W, bias);
    k_crf<<<BB*NC, 96>>>(trans, mask, labels, startv, endv, (float*)d_out);
}